// round 15
// baseline (speedup 1.0000x reference)
#include <cuda_runtime.h>

#define NB   2
#define NE   8
#define NPX  4096      // 64*64
#define KTOP 700
#define NG   4
#define NCH  36        // (NE+1)*NG
#define OUTW 256

__device__ int g_topk_idx[NB * KTOP];

__device__ __forceinline__ float frcp(float x) {
    float r;
    asm("rcp.approx.f32 %0, %1;" : "=f"(r) : "f"(x));
    return r;
}

// ---------------------------------------------------------------------------
// Kernel 1: exact top-k by HISTOGRAM-PRUNED rank counting.
// Grid (32, NB): each block caches all 4096 monotonic keys (16 KB), finds
// the exact top-byte bin of the 700th key via histogram + suffix scan, then
// fully ranks only its owned candidates (~28 of 128). 4x less total load
// traffic than the (128, NB) version.
// ---------------------------------------------------------------------------
__global__ __launch_bounds__(256)
void topk_kernel(const float* __restrict__ obj,
                 float* __restrict__ scores) {
    __shared__ unsigned key[NPX];     // 16 KB
    __shared__ int hist[256];
    __shared__ int thr_bin;
    const int b    = blockIdx.y;
    const int tid  = threadIdx.x;
    const int base = blockIdx.x * 128;
    const float* p = obj + b * NPX;

    hist[tid] = 0;
    __syncthreads();
    for (int i = tid; i < NPX; i += 256) {
        unsigned u = __float_as_uint(p[i]);
        u ^= (unsigned)(((int)u >> 31) | 0x80000000);   // monotonic map
        key[i] = u;
        atomicAdd(&hist[u >> 24], 1);
    }
    __syncthreads();

    if (tid < 32) {
        int s = 0;
#pragma unroll
        for (int q = 0; q < 8; q++) s += hist[tid * 8 + q];
        int suf = s;                       // inclusive suffix-sum over lanes
#pragma unroll
        for (int d = 1; d < 32; d <<= 1) {
            int o = __shfl_down_sync(0xffffffffu, suf, d);
            if (tid + d < 32) suf += o;
        }
        unsigned m = __ballot_sync(0xffffffffu, suf >= KTOP);
        int L = 31 - __clz(m);
        int sufn = __shfl_down_sync(0xffffffffu, suf, 1);
        if (tid == L) {
            int c = (L == 31) ? 0 : sufn;
            int bb = L * 8 + 7;
            while (c + hist[bb] < KTOP) { c += hist[bb]; bb--; }
            thr_bin = bb;                  // bin containing the 700th key
        }
    }
    __syncthreads();
    const unsigned T = (unsigned)thr_bin;
    const int warp = tid >> 5, lane = tid & 31;

    for (int c = warp; c < 128; c += 8) {
        const int e = base + c;
        const unsigned me = key[e];
        if ((me >> 24) < T) continue;      // cannot be in top-700
        int cnt = 0;
#pragma unroll 4
        for (int t = 0; t < 128; t++) {
            const int i = lane + (t << 5);
            const unsigned ki = key[i];
            cnt += (ki > me) || (ki == me && i < e);
        }
        cnt += __shfl_down_sync(0xffffffffu, cnt, 16);
        cnt += __shfl_down_sync(0xffffffffu, cnt, 8);
        cnt += __shfl_down_sync(0xffffffffu, cnt, 4);
        cnt += __shfl_down_sync(0xffffffffu, cnt, 2);
        cnt += __shfl_down_sync(0xffffffffu, cnt, 1);
        if (lane == 0 && cnt < KTOP) {
            scores[b * KTOP + cnt] = frcp(1.0f + __expf(-p[e]));
            g_topk_idx[b * KTOP + cnt] = e;
        }
    }
}

// ---------------------------------------------------------------------------
// Helpers for the mask kernel (R11-proven float2 compute + column-walk).
// ---------------------------------------------------------------------------
__device__ __forceinline__ void compute_low(float* low,
                                            const volatile float* vw,
                                            const float2* encb, int tid) {
#pragma unroll
    for (int it = 0; it < 8; it++) {
        const int q = it * 256 + tid;   // float2 index in 64x64 plane
        float2 ev[NE];
#pragma unroll
        for (int e = 0; e < NE; e++)
            ev[e] = __ldg(encb + e * (NPX / 2) + q);

        float px = 1.f, py = 1.f;
#pragma unroll
        for (int g = 0; g < NG; g++) {
            float ax = vw[g * (NE + 1) + NE];
            float ay = ax;
#pragma unroll
            for (int e = 0; e < NE; e++) {
                const float w = vw[g * (NE + 1) + e];
                ax = fmaf(w, ev[e].x, ax);
                ay = fmaf(w, ev[e].y, ay);
            }
            px *= 1.f + __expf(-ax);
            py *= 1.f + __expf(-ay);
        }
        ((float2*)low)[q] = make_float2(frcp(px), frcp(py));
    }
}

// Column-walk 4x bilinear upsample: output rows 4m+p take input rows (m-1,m)
// for p=0,1 (fy 0.625, 0.875) and (m,m+1) for p=2,3 (fy 0.125, 0.375);
// clamps collapse to the edge row, matching jax half-pixel bilinear.
__device__ __forceinline__ void store_up(const float* low, float* obase,
                                         int tid) {
    const int j  = tid & 63;        // float4 column
    const int q4 = tid >> 6;        // row quarter
    const int jp = (j == 0)  ? 0  : j - 1;
    const int jn = (j == 63) ? 63 : j + 1;
    const int m0 = q4 * 16;

    float* orow = obase + (q4 * 64) * OUTW + j * 4;

    float ap, ac, an, bp, bc, bn;
    {
        const float* ra = low + ((m0 == 0) ? 0 : m0 - 1) * 64;
        ap = ra[jp]; ac = ra[j]; an = ra[jn];
        const float* rb = low + m0 * 64;
        bp = rb[jp]; bc = rb[j]; bn = rb[jn];
    }

#pragma unroll 1
    for (int m = m0; m < m0 + 16; m++) {
        const int mn = (m >= 63) ? 63 : m + 1;
        const float* rc = low + mn * 64;
        const float cp = rc[jp], cc = rc[j], cn = rc[jn];

#pragma unroll
        for (int p = 0; p < 4; p++) {
            const float fy = (p == 0) ? 0.625f : (p == 1) ? 0.875f
                           : (p == 2) ? 0.125f : 0.375f;
            float vp, vc, vn;
            if (p < 2) {
                vp = fmaf(fy, bp - ap, ap);
                vc = fmaf(fy, bc - ac, ac);
                vn = fmaf(fy, bn - an, an);
            } else {
                vp = fmaf(fy, cp - bp, bp);
                vc = fmaf(fy, cc - bc, bc);
                vn = fmaf(fy, cn - bn, bn);
            }
            const float dp = vp - vc, dn = vn - vc;
            float4 o;
            o.x = fmaf(0.375f, dp, vc);
            o.y = fmaf(0.125f, dp, vc);
            o.z = fmaf(0.125f, dn, vc);
            o.w = fmaf(0.375f, dn, vc);
            __stcs((float4*)(orow + p * OUTW), o);
        }
        ap = bp; ac = bc; an = bn;
        bp = cp; bc = cc; bn = cn;
        orow += 4 * OUTW;
    }
}

// ---------------------------------------------------------------------------
// Kernel 2: TWO detections per block, phase-mixed barrier intervals.
//   C(low0) | sync | S(out0) ; C(low1) | sync | S(out1)
// The middle interval has no barrier between store and compute, so warps
// drift: some issue STG while others run FMA/MUFU -> mixed LSU+math issue
// stream for ~2/3 of the kernel (the mono-phase alternation left DRAM idle
// 37% and issue at 42%). Grid (350, NB) = 700 blocks = exactly one wave.
// ---------------------------------------------------------------------------
__global__ __launch_bounds__(256, 6)
void mask_kernel(const float* __restrict__ enc,   // (NB, NE, 64, 64)
                 const float* __restrict__ wts,   // (NB, NCH, 64, 64)
                 float* __restrict__ out) {       // (NB, KTOP, 256, 256)
    __shared__ float low0[NPX];
    __shared__ float low1[NPX];
    __shared__ float swt[2 * NCH];

    const int kx  = blockIdx.x;
    const int b   = blockIdx.y;
    const int tid = threadIdx.x;
    const int k0  = 2 * kx, k1 = 2 * kx + 1;

    if (tid < 2 * NCH) {
        const int which = (tid < NCH) ? 0 : 1;
        const int ch    = (tid < NCH) ? tid : tid - NCH;
        const int pos   = g_topk_idx[b * KTOP + (which ? k1 : k0)];
        swt[tid] = wts[(b * NCH + ch) * NPX + pos];
    }
    __syncthreads();

    const volatile float* vw = swt;     // keep weights in LDS, regs low
    const float2* encb = (const float2*)(enc + b * NE * NPX);
    float* ob0 = out + ((size_t)(b * KTOP + k0)) * (OUTW * OUTW);
    float* ob1 = out + ((size_t)(b * KTOP + k1)) * (OUTW * OUTW);

    compute_low(low0, vw, encb, tid);
    __syncthreads();

    // mixed interval: stores of mask0 overlap compute of mask1 via warp drift
    store_up(low0, ob0, tid);
    compute_low(low1, vw + NCH, encb, tid);
    __syncthreads();

    store_up(low1, ob1, tid);
}

// ---------------------------------------------------------------------------
extern "C" void kernel_launch(void* const* d_in, const int* in_sizes, int n_in,
                              void* d_out, int out_size) {
    const float* obj = (const float*)d_in[0];  // objectness_logits (2,1,64,64)
    const float* enc = (const float*)d_in[1];  // mask_encodings   (2,8,64,64)
    const float* wts = (const float*)d_in[2];  // weights          (2,36,64,64)
    float* out    = (float*)d_out;             // m (2,700,256,256) then scores
    float* scores = out + (size_t)NB * KTOP * OUTW * OUTW;

    dim3 tg(32, NB);
    topk_kernel<<<tg, 256>>>(obj, scores);
    dim3 grid(KTOP / 2, NB);
    mask_kernel<<<grid, 256>>>(enc, wts, out);
}

// round 16
// speedup vs baseline: 1.3911x; 1.3911x over previous
#include <cuda_runtime.h>

#define NB    2
#define NE    8
#define NPX   4096      // 64*64
#define KTOP  700
#define NG    4
#define NCH   36        // (NE+1)*NG
#define OUTW  256
#define NBLK  296       // 2 blocks per SM exactly
#define NUNIT 2800      // NB*KTOP*2 half-planes
#define BROWS 33        // input rows buffered per half (32 + 1 halo)

__device__ int g_topk_idx[NB * KTOP];

__device__ __forceinline__ float frcp(float x) {
    float r;
    asm("rcp.approx.f32 %0, %1;" : "=f"(r) : "f"(x));
    return r;
}

// ---------------------------------------------------------------------------
// Kernel 1: exact top-k by histogram-pruned rank counting (R11-measured).
// ---------------------------------------------------------------------------
__global__ __launch_bounds__(256)
void topk_kernel(const float* __restrict__ obj,
                 float* __restrict__ scores) {
    __shared__ unsigned key[NPX];     // 16 KB
    __shared__ int hist[256];
    __shared__ int thr_bin;
    const int b    = blockIdx.y;
    const int tid  = threadIdx.x;
    const int base = blockIdx.x * 32;
    const float* p = obj + b * NPX;

    hist[tid] = 0;
    __syncthreads();
    for (int i = tid; i < NPX; i += 256) {
        unsigned u = __float_as_uint(p[i]);
        u ^= (unsigned)(((int)u >> 31) | 0x80000000);   // monotonic map
        key[i] = u;
        atomicAdd(&hist[u >> 24], 1);
    }
    __syncthreads();

    if (tid < 32) {
        int s = 0;
#pragma unroll
        for (int q = 0; q < 8; q++) s += hist[tid * 8 + q];
        int suf = s;
#pragma unroll
        for (int d = 1; d < 32; d <<= 1) {
            int o = __shfl_down_sync(0xffffffffu, suf, d);
            if (tid + d < 32) suf += o;
        }
        unsigned m = __ballot_sync(0xffffffffu, suf >= KTOP);
        int L = 31 - __clz(m);
        int sufn = __shfl_down_sync(0xffffffffu, suf, 1);
        if (tid == L) {
            int c = (L == 31) ? 0 : sufn;
            int bb = L * 8 + 7;
            while (c + hist[bb] < KTOP) { c += hist[bb]; bb--; }
            thr_bin = bb;
        }
    }
    __syncthreads();
    const unsigned T = (unsigned)thr_bin;
    const int warp = tid >> 5, lane = tid & 31;

    for (int c = warp; c < 32; c += 8) {
        const int e = base + c;
        const unsigned me = key[e];
        if ((me >> 24) < T) continue;
        int cnt = 0;
#pragma unroll 4
        for (int t = 0; t < 128; t++) {
            const int i = lane + (t << 5);
            const unsigned ki = key[i];
            cnt += (ki > me) || (ki == me && i < e);
        }
        cnt += __shfl_down_sync(0xffffffffu, cnt, 16);
        cnt += __shfl_down_sync(0xffffffffu, cnt, 8);
        cnt += __shfl_down_sync(0xffffffffu, cnt, 4);
        cnt += __shfl_down_sync(0xffffffffu, cnt, 2);
        cnt += __shfl_down_sync(0xffffffffu, cnt, 1);
        if (lane == 0 && cnt < KTOP) {
            scores[b * KTOP + cnt] = frcp(1.0f + __expf(-p[e]));
            g_topk_idx[b * KTOP + cnt] = e;
        }
    }
}

// ---------------------------------------------------------------------------
// Kernel 2: persistent WARP-SPECIALIZED producer/consumer.
// 296 blocks (2/SM). Warps 4-7 = producers: compute the 33-input-row half
// mask into a double-buffered SMEM slab. Warps 0-3 = consumers: column-walk
// 4x bilinear upsample, 128 KB of STG.128 per unit, ALWAYS storing. Unit
// u = bid + 296*s, decode (kk = plane, half). Step s: produce(u_s) into
// buf[s&1] || consume(u_{s-1}) from buf[(s-1)&1]; __syncthreads.
// Producers finish early and wait; consumers backpressure on the LSU/L2
// queues -> DRAM write stream is continuous for ~(n-1)/n of the kernel
// (mono-phase alternation capped DRAM active at 63% across R3/R7/R11).
// ---------------------------------------------------------------------------
__global__ __launch_bounds__(256)
void mask_kernel(const float* __restrict__ enc,   // (NB, NE, 64, 64)
                 const float* __restrict__ wts,   // (NB, NCH, 64, 64)
                 float* __restrict__ out) {       // (NB, KTOP, 256, 256)
    __shared__ float lowb[2][BROWS * 64];   // 2 x 8448 B
    __shared__ float wbuf[NCH];

    const int bid = blockIdx.x;
    const int tid = threadIdx.x;
    const bool prod = (tid >= 128);
    const int n = (NUNIT - bid + NBLK - 1) / NBLK;   // units for this block

    for (int s = 0; s <= n; s++) {
        // ---------------- producers: compute unit s ----------------
        if (prod && s < n) {
            const int u  = bid + NBLK * s;
            const int h  = u & 1;
            const int kk = u >> 1;                 // global plane 0..1399
            const int b  = (kk >= KTOP) ? 1 : 0;
            const int pt = tid - 128;

            if (pt < NCH) {
                const int pos = g_topk_idx[kk];    // kk == b*KTOP + k
                wbuf[pt] = wts[(b * NCH + pt) * NPX + pos];
            }
            asm volatile("bar.sync 1, 128;");      // producer-group barrier

            const volatile float* vw = wbuf;
            const float2* encb = (const float2*)(enc + b * NE * NPX);
            float2* low2 = (float2*)lowb[s & 1];
            const int r_lo = h * 31;               // top: rows 0..32, bottom: 31..63

#pragma unroll 1
            for (int p = pt; p < BROWS * 32; p += 128) {
                const int q = (r_lo + (p >> 5)) * 32 + (p & 31);  // global f2 idx
                float2 ev[NE];
#pragma unroll
                for (int e = 0; e < NE; e++)
                    ev[e] = __ldg(encb + e * (NPX / 2) + q);

                float px = 1.f, py = 1.f;
#pragma unroll
                for (int g = 0; g < NG; g++) {
                    float ax = vw[g * (NE + 1) + NE];
                    float ay = ax;
#pragma unroll
                    for (int e = 0; e < NE; e++) {
                        const float w = vw[g * (NE + 1) + e];
                        ax = fmaf(w, ev[e].x, ax);
                        ay = fmaf(w, ev[e].y, ay);
                    }
                    px *= 1.f + __expf(-ax);
                    py *= 1.f + __expf(-ay);
                }
                low2[p] = make_float2(frcp(px), frcp(py));
            }
        }

        // ---------------- consumers: store unit s-1 ----------------
        if (!prod && s >= 1) {
            const int u  = bid + NBLK * (s - 1);
            const int h  = u & 1;
            const int kk = u >> 1;
            const float* low = lowb[(s - 1) & 1];
            const int r_lo = h * 31;

            const int j  = tid & 63;         // float4 column
            const int q  = tid >> 6;         // quarter within half (0/1)
            const int jp = (j == 0)  ? 0  : j - 1;
            const int jn = (j == 63) ? 63 : j + 1;
            const int m0 = h * 32 + q * 16;  // first input row this thread walks

            float* orow = out + (size_t)kk * (OUTW * OUTW)
                              + (4 * m0) * OUTW + j * 4;

            // rolling 3-tap window (buffer-relative row = m - r_lo)
            float ap, ac, an, bp, bc, bn;
            {
                const int ma = (m0 == 0) ? 0 : m0 - 1;
                const float* ra = low + (ma - r_lo) * 64;
                ap = ra[jp]; ac = ra[j]; an = ra[jn];
                const float* rb = low + (m0 - r_lo) * 64;
                bp = rb[jp]; bc = rb[j]; bn = rb[jn];
            }

#pragma unroll 1
            for (int m = m0; m < m0 + 16; m++) {
                const int mn = (m >= 63) ? 63 : m + 1;
                const float* rc = low + (mn - r_lo) * 64;
                const float cp = rc[jp], cc = rc[j], cn = rc[jn];

#pragma unroll
                for (int p = 0; p < 4; p++) {
                    const float fy = (p == 0) ? 0.625f : (p == 1) ? 0.875f
                                   : (p == 2) ? 0.125f : 0.375f;
                    float vp, vc, vn;
                    if (p < 2) {
                        vp = fmaf(fy, bp - ap, ap);
                        vc = fmaf(fy, bc - ac, ac);
                        vn = fmaf(fy, bn - an, an);
                    } else {
                        vp = fmaf(fy, cp - bp, bp);
                        vc = fmaf(fy, cc - bc, bc);
                        vn = fmaf(fy, cn - bn, bn);
                    }
                    const float dp = vp - vc, dn = vn - vc;
                    float4 o;
                    o.x = fmaf(0.375f, dp, vc);
                    o.y = fmaf(0.125f, dp, vc);
                    o.z = fmaf(0.125f, dn, vc);
                    o.w = fmaf(0.375f, dn, vc);
                    __stcs((float4*)(orow + p * OUTW), o);
                }
                ap = bp; ac = bc; an = bn;
                bp = cp; bc = cc; bn = cn;
                orow += 4 * OUTW;
            }
        }
        __syncthreads();
    }
}

// ---------------------------------------------------------------------------
extern "C" void kernel_launch(void* const* d_in, const int* in_sizes, int n_in,
                              void* d_out, int out_size) {
    const float* obj = (const float*)d_in[0];  // objectness_logits (2,1,64,64)
    const float* enc = (const float*)d_in[1];  // mask_encodings   (2,8,64,64)
    const float* wts = (const float*)d_in[2];  // weights          (2,36,64,64)
    float* out    = (float*)d_out;             // m (2,700,256,256) then scores
    float* scores = out + (size_t)NB * KTOP * OUTW * OUTW;

    dim3 tg(128, NB);
    topk_kernel<<<tg, 256>>>(obj, scores);
    mask_kernel<<<NBLK, 256>>>(enc, wts, out);
}

// round 17
// speedup vs baseline: 1.9197x; 1.3800x over previous
#include <cuda_runtime.h>

#define NB   2
#define NE   8
#define NPX  4096      // 64*64
#define KTOP 700
#define NG   4
#define NCH  36        // (NE+1)*NG
#define OUTW 256

__device__ int g_topk_idx[NB * KTOP];

__device__ __forceinline__ float frcp(float x) {
    float r;
    asm("rcp.approx.f32 %0, %1;" : "=f"(r) : "f"(x));
    return r;
}

__device__ __forceinline__ unsigned mono(float f) {
    unsigned u = __float_as_uint(f);
    return u ^ (unsigned)(((int)u >> 31) | 0x80000000);
}

// ---------------------------------------------------------------------------
// Kernel 1: exact top-k by histogram-pruned rank counting (R10/R11-measured
// config), with float4 load phase and an early PDL trigger so the mask
// grid's dispatch overlaps this kernel's tail.
// ---------------------------------------------------------------------------
__global__ __launch_bounds__(256)
void topk_kernel(const float* __restrict__ obj,
                 float* __restrict__ scores) {
    __shared__ unsigned key[NPX];     // 16 KB
    __shared__ int hist[256];
    __shared__ int thr_bin;
    const int b    = blockIdx.y;
    const int tid  = threadIdx.x;
    const int base = blockIdx.x * 32;
    const float* p = obj + b * NPX;

    hist[tid] = 0;
    __syncthreads();
    {
        const float4* p4 = (const float4*)p;
#pragma unroll
        for (int i = tid; i < NPX / 4; i += 256) {
            const float4 v = __ldg(p4 + i);
            uint4 kk;
            kk.x = mono(v.x); kk.y = mono(v.y);
            kk.z = mono(v.z); kk.w = mono(v.w);
            ((uint4*)key)[i] = kk;
            atomicAdd(&hist[kk.x >> 24], 1);
            atomicAdd(&hist[kk.y >> 24], 1);
            atomicAdd(&hist[kk.z >> 24], 1);
            atomicAdd(&hist[kk.w >> 24], 1);
        }
    }
    __syncthreads();

    if (tid < 32) {
        int s = 0;
#pragma unroll
        for (int q = 0; q < 8; q++) s += hist[tid * 8 + q];
        int suf = s;                       // inclusive suffix-sum over lanes
#pragma unroll
        for (int d = 1; d < 32; d <<= 1) {
            int o = __shfl_down_sync(0xffffffffu, suf, d);
            if (tid + d < 32) suf += o;
        }
        unsigned m = __ballot_sync(0xffffffffu, suf >= KTOP);
        int L = 31 - __clz(m);
        int sufn = __shfl_down_sync(0xffffffffu, suf, 1);
        if (tid == L) {
            int c = (L == 31) ? 0 : sufn;
            int bb = L * 8 + 7;
            while (c + hist[bb] < KTOP) { c += hist[bb]; bb--; }
            thr_bin = bb;                  // bin containing the 700th key
        }
    }
    __syncthreads();
    const unsigned T = (unsigned)thr_bin;
    const int warp = tid >> 5, lane = tid & 31;

    for (int c = warp; c < 32; c += 8) {
        const int e = base + c;
        const unsigned me = key[e];
        if ((me >> 24) < T) continue;      // cannot be in top-700
        int cnt = 0;
#pragma unroll 4
        for (int t = 0; t < 128; t++) {
            const int i = lane + (t << 5);
            const unsigned ki = key[i];
            cnt += (ki > me) || (ki == me && i < e);
        }
        cnt += __shfl_down_sync(0xffffffffu, cnt, 16);
        cnt += __shfl_down_sync(0xffffffffu, cnt, 8);
        cnt += __shfl_down_sync(0xffffffffu, cnt, 4);
        cnt += __shfl_down_sync(0xffffffffu, cnt, 2);
        cnt += __shfl_down_sync(0xffffffffu, cnt, 1);
        if (lane == 0 && cnt < KTOP) {
            scores[b * KTOP + cnt] = frcp(1.0f + __expf(-p[e]));
            g_topk_idx[b * KTOP + cnt] = e;
        }
    }

    // Publish scatters, then allow the dependent mask grid to launch.
    __threadfence();
    asm volatile("griddepcontrol.launch_dependents;");
}

// ---------------------------------------------------------------------------
// Kernel 2: measured-best mask kernel (R10/R11, 62.0us, at the HBM write
// floor). One block per (b, k): float2 group-product mask compute into SMEM,
// then column-walk 4x bilinear upsample (rolling 3-tap register window,
// 3 LDS per 4 STG.128). Entry gates on the PDL wait before reading topk.
// ---------------------------------------------------------------------------
__global__ __launch_bounds__(256, 6)
void mask_kernel(const float* __restrict__ enc,   // (NB, NE, 64, 64)
                 const float* __restrict__ wts,   // (NB, NCH, 64, 64)
                 float* __restrict__ out) {       // (NB, KTOP, 256, 256)
    __shared__ float low[NPX];
    __shared__ float swt[NCH];

    const int k   = blockIdx.x;
    const int b   = blockIdx.y;
    const int tid = threadIdx.x;

    asm volatile("griddepcontrol.wait;" ::: "memory");

    const int pos = g_topk_idx[b * KTOP + k];
    if (tid < NCH) swt[tid] = wts[(b * NCH + tid) * NPX + pos];
    __syncthreads();

    const volatile float* vw = swt;     // keep weights in LDS, regs low
    const float2* encb = (const float2*)(enc + b * NE * NPX);

#pragma unroll
    for (int it = 0; it < 8; it++) {
        const int q = it * 256 + tid;   // float2 index in 64x64 plane
        float2 ev[NE];
#pragma unroll
        for (int e = 0; e < NE; e++)
            ev[e] = __ldg(encb + e * (NPX / 2) + q);

        float px = 1.f, py = 1.f;
#pragma unroll
        for (int g = 0; g < NG; g++) {
            float ax = vw[g * (NE + 1) + NE];
            float ay = ax;
#pragma unroll
            for (int e = 0; e < NE; e++) {
                const float w = vw[g * (NE + 1) + e];
                ax = fmaf(w, ev[e].x, ax);
                ay = fmaf(w, ev[e].y, ay);
            }
            px *= 1.f + __expf(-ax);
            py *= 1.f + __expf(-ay);
        }
        ((float2*)low)[q] = make_float2(frcp(px), frcp(py));
    }
    __syncthreads();

    // Column-walk upsample: output rows 4m+p take input rows (m-1,m) for
    // p=0,1 (fy 0.625, 0.875) and (m,m+1) for p=2,3 (fy 0.125, 0.375);
    // clamps collapse to the edge row, matching jax half-pixel bilinear.
    {
        const int j  = tid & 63;        // float4 column
        const int q4 = tid >> 6;        // row quarter
        const int jp = (j == 0)  ? 0  : j - 1;
        const int jn = (j == 63) ? 63 : j + 1;
        const int m0 = q4 * 16;

        float* orow = out + ((size_t)(b * KTOP + k)) * (OUTW * OUTW)
                          + (q4 * 64) * OUTW + j * 4;

        float ap, ac, an, bp, bc, bn;
        {
            const float* ra = low + ((m0 == 0) ? 0 : m0 - 1) * 64;
            ap = ra[jp]; ac = ra[j]; an = ra[jn];
            const float* rb = low + m0 * 64;
            bp = rb[jp]; bc = rb[j]; bn = rb[jn];
        }

#pragma unroll 1
        for (int m = m0; m < m0 + 16; m++) {
            const int mn = (m >= 63) ? 63 : m + 1;
            const float* rc = low + mn * 64;
            const float cp = rc[jp], cc = rc[j], cn = rc[jn];

#pragma unroll
            for (int p = 0; p < 4; p++) {
                const float fy = (p == 0) ? 0.625f : (p == 1) ? 0.875f
                               : (p == 2) ? 0.125f : 0.375f;
                float vp, vc, vn;
                if (p < 2) {
                    vp = fmaf(fy, bp - ap, ap);
                    vc = fmaf(fy, bc - ac, ac);
                    vn = fmaf(fy, bn - an, an);
                } else {
                    vp = fmaf(fy, cp - bp, bp);
                    vc = fmaf(fy, cc - bc, bc);
                    vn = fmaf(fy, cn - bn, bn);
                }
                const float dp = vp - vc, dn = vn - vc;
                float4 o;
                o.x = fmaf(0.375f, dp, vc);
                o.y = fmaf(0.125f, dp, vc);
                o.z = fmaf(0.125f, dn, vc);
                o.w = fmaf(0.375f, dn, vc);
                __stcs((float4*)(orow + p * OUTW), o);
            }
            ap = bp; ac = bc; an = bn;
            bp = cp; bc = cc; bn = cn;
            orow += 4 * OUTW;
        }
    }
}

// ---------------------------------------------------------------------------
extern "C" void kernel_launch(void* const* d_in, const int* in_sizes, int n_in,
                              void* d_out, int out_size) {
    const float* obj = (const float*)d_in[0];  // objectness_logits (2,1,64,64)
    const float* enc = (const float*)d_in[1];  // mask_encodings   (2,8,64,64)
    const float* wts = (const float*)d_in[2];  // weights          (2,36,64,64)
    float* out    = (float*)d_out;             // m (2,700,256,256) then scores
    float* scores = out + (size_t)NB * KTOP * OUTW * OUTW;

    dim3 tg(128, NB);
    topk_kernel<<<tg, 256>>>(obj, scores);

    // Mask kernel launched with programmatic dependency: its blocks may be
    // dispatched while topk still runs; griddepcontrol.wait gates the
    // g_topk_idx read until topk's launch_dependents fires.
    cudaLaunchConfig_t cfg = {};
    cfg.gridDim  = dim3(KTOP, NB);
    cfg.blockDim = dim3(256, 1, 1);
    cfg.dynamicSmemBytes = 0;
    cfg.stream = 0;
    cudaLaunchAttribute attr[1];
    attr[0].id = cudaLaunchAttributeProgrammaticStreamSerialization;
    attr[0].val.programmaticStreamSerializationAllowed = 1;
    cfg.attrs = attr;
    cfg.numAttrs = 1;
    cudaLaunchKernelEx(&cfg, mask_kernel, enc, wts, out);
}